// round 6
// baseline (speedup 1.0000x reference)
#include <cuda_runtime.h>

#define IH 384
#define IW 384
#define HO 382
#define WO 382
#define NB 8
#define HALO 6
#define TH 22          // rows [ho0-6, ho0+15]
#define TW 46          // cols [wo0-6, wo0+39]
#define TILE_CH (TH * TW)   // 1012

typedef unsigned long long u64;

__device__ __forceinline__ u64 fma2(u64 a, u64 b, u64 c) {
    u64 d;
    asm("fma.rn.f32x2 %0, %1, %2, %3;" : "=l"(d) : "l"(a), "l"(b), "l"(c));
    return d;
}
__device__ __forceinline__ u64 pack2(float lo, float hi) {
    u64 r;
    asm("mov.b64 %0, {%1, %2};" : "=l"(r) : "f"(lo), "f"(hi));
    return r;
}
__device__ __forceinline__ void unpack2(u64 v, float& lo, float& hi) {
    asm("mov.b64 {%0, %1}, %2;" : "=f"(lo), "=f"(hi) : "l"(v));
}

__global__ __launch_bounds__(128, 4)
void deform_fused6(const float* __restrict__ x,
                   const float* __restrict__ w1,
                   const float* __restrict__ b1,
                   const float* __restrict__ w2,
                   const float* __restrict__ b2,
                   float* __restrict__ out)
{
    __shared__ float4 s_tile4[TILE_CH];            // (ch0, ch1, ch2, pad), zero outside image
    __shared__ __align__(16) u64 s_w1p[9 * 28];    // [kk][j] packed (wdy, wdx); slot 27 = 0 pad
    __shared__ u64 s_b1p[9];
    __shared__ __align__(16) float4 s_w2v[9 * 3];  // [kk][c] = (w2[o=0], w2[o=1], w2[o=2], 0)
    __shared__ float s_b2[3];

    const int tid = threadIdx.y * 32 + threadIdx.x;

    // ---- weights to shared ----
    for (int i = tid; i < 9 * 27; i += 128) {
        int kk = i / 27, j = i % 27;
        s_w1p[kk * 28 + j] = pack2(w1[(2 * kk) * 27 + j], w1[(2 * kk + 1) * 27 + j]);
    }
    for (int i = tid; i < 9; i += 128) {
        s_w1p[i * 28 + 27] = 0ull;                 // zero pad slot (pairs the j-loop evenly)
        s_b1p[i] = pack2(b1[2 * i], b1[2 * i + 1]);
    }
    if (tid < 27) {
        int kk = tid / 3, c = tid % 3;
        s_w2v[kk * 3 + c] = make_float4(w2[0 * 27 + c * 9 + kk],
                                        w2[1 * 27 + c * 9 + kk],
                                        w2[2 * 27 + c * 9 + kk], 0.f);
    }
    if (tid < 3) s_b2[tid] = b2[tid];

    const int wo0 = blockIdx.x * 32;
    const int ho0 = blockIdx.y * 8;
    const int b   = blockIdx.z;
    const float* __restrict__ xb = x + (size_t)b * 3 * IH * IW;

    const int rowBase = ho0 - HALO;
    const int colBase = wo0 - HALO;

    // ---- input tile to shared, channel-interleaved (zero-filled outside image) ----
    for (int i = tid; i < TILE_CH; i += 128) {
        int r   = i / TW;
        int col = i - r * TW;
        int gy = rowBase + r;
        int gx = colBase + col;
        float v0 = 0.f, v1 = 0.f, v2 = 0.f;
        if ((unsigned)gy < IH && (unsigned)gx < IW) {
            const float* p = xb + (size_t)gy * IW + gx;
            v0 = __ldg(p);
            v1 = __ldg(p + IH * IW);
            v2 = __ldg(p + 2 * IH * IW);
        }
        s_tile4[i] = make_float4(v0, v1, v2, 0.f);
    }
    __syncthreads();

    const int wo  = wo0 + threadIdx.x;
    const int hoA = ho0 + 2 * threadIdx.y;   // pixel pair rows hoA, hoA+1
    const int ltx = threadIdx.x + HALO;
    const int lty = 2 * threadIdx.y + HALO;

    // ---- window (4 rows x 3 cols x 3 ch) duplicated-packed in registers ----
    // wr2f[c*12 + r*3 + kw] = dup(window value)
    u64 wr2f[36];
#pragma unroll
    for (int r = 0; r < 4; r++)
#pragma unroll
        for (int kw = 0; kw < 3; kw++) {
            float4 q = s_tile4[(lty + r) * TW + (ltx + kw)];
            wr2f[0 * 12 + r * 3 + kw] = pack2(q.x, q.x);
            wr2f[1 * 12 + r * 3 + kw] = pack2(q.y, q.y);
            wr2f[2 * 12 + r * 3 + kw] = pack2(q.z, q.z);
        }

    float acc[2][3];
#pragma unroll
    for (int p = 0; p < 2; p++)
#pragma unroll
        for (int o = 0; o < 3; o++) acc[p][o] = s_b2[o];

#pragma unroll 1
    for (int kk = 0; kk < 9; kk++) {
        // ---- offset conv for this kk, both pixels, packed (dy,dx); paired LDS.128 weights ----
        u64 a0 = s_b1p[kk];
        u64 a1 = a0;
        const ulonglong2* __restrict__ wq = (const ulonglong2*)&s_w1p[kk * 28];
#pragma unroll
        for (int jj = 0; jj < 14; jj++) {
            ulonglong2 w = wq[jj];
            {
                const int j = 2 * jj;
                const int c = j / 9, kh = (j / 3) % 3, kw = j % 3;
                a0 = fma2(wr2f[c * 12 + kh * 3 + kw],       w.x, a0);
                a1 = fma2(wr2f[c * 12 + (kh + 1) * 3 + kw], w.x, a1);
            }
            {
                const int j2 = 2 * jj + 1;
                const int j = (j2 < 27) ? j2 : 0;   // j=27 is the zero-pad weight: adds 0
                const int c = j / 9, kh = (j / 3) % 3, kw = j % 3;
                a0 = fma2(wr2f[c * 12 + kh * 3 + kw],       w.y, a0);
                a1 = fma2(wr2f[c * 12 + (kh + 1) * 3 + kw], w.y, a1);
            }
        }

        const int kh = kk / 3;
        const int kw = kk - 3 * kh;

        // w2 for this kk (shared across both pixels)
        float4 w40 = s_w2v[kk * 3 + 0];
        float4 w41 = s_w2v[kk * 3 + 1];
        float4 w42 = s_w2v[kk * 3 + 2];

#pragma unroll
        for (int p = 0; p < 2; p++) {
            float dy, dx;
            unpack2(p ? a1 : a0, dy, dx);
            float py = (float)(hoA + p + kh) + dy;
            float px = (float)(wo + kw) + dx;
            int y0 = __float2int_rd(py);
            int x0 = __float2int_rd(px);
            float wy = py - (float)y0;
            float wx = px - (float)x0;

            float c00 = (1.f - wy) * (1.f - wx);
            float c01 = (1.f - wy) * wx;
            float c10 = wy * (1.f - wx);
            float c11 = wy * wx;

            int ly0 = y0 - rowBase;
            int lx0 = x0 - colBase;

            float v0, v1, v2;
            if ((unsigned)ly0 <= TH - 2 && (unsigned)lx0 <= TW - 2) {
                // fast path: 4 x LDS.128; zero-filled tile makes validity masks redundant
                int t = ly0 * TW + lx0;
                float4 q00 = s_tile4[t];
                float4 q01 = s_tile4[t + 1];
                float4 q10 = s_tile4[t + TW];
                float4 q11 = s_tile4[t + TW + 1];
                v0 = fmaf(c11, q11.x, fmaf(c10, q10.x, fmaf(c01, q01.x, c00 * q00.x)));
                v1 = fmaf(c11, q11.y, fmaf(c10, q10.y, fmaf(c01, q01.y, c00 * q00.y)));
                v2 = fmaf(c11, q11.z, fmaf(c10, q10.z, fmaf(c01, q01.z, c00 * q00.z)));
            } else {
                // rare slow path: clamped global loads (exact reference semantics)
                bool vy0 = (y0 >= 0)  && (y0 <= IH - 1);
                bool vy1 = (y0 >= -1) && (y0 <= IH - 2);
                bool vx0 = (x0 >= 0)  && (x0 <= IW - 1);
                bool vx1 = (x0 >= -1) && (x0 <= IW - 2);
                float m00 = c00 * ((vy0 && vx0) ? 1.f : 0.f);
                float m01 = c01 * ((vy0 && vx1) ? 1.f : 0.f);
                float m10 = c10 * ((vy1 && vx0) ? 1.f : 0.f);
                float m11 = c11 * ((vy1 && vx1) ? 1.f : 0.f);
                int yc0 = min(max(y0, 0), IH - 1);
                int yc1 = min(max(y0 + 1, 0), IH - 1);
                int xc0 = min(max(x0, 0), IW - 1);
                int xc1 = min(max(x0 + 1, 0), IW - 1);
                int i00 = yc0 * IW + xc0;
                int i01 = yc0 * IW + xc1;
                int i10 = yc1 * IW + xc0;
                int i11 = yc1 * IW + xc1;
                float vv[3];
#pragma unroll
                for (int c = 0; c < 3; c++) {
                    const float* __restrict__ xc = xb + (size_t)c * IH * IW;
                    vv[c] = m00 * __ldg(xc + i00) + m01 * __ldg(xc + i01)
                          + m10 * __ldg(xc + i10) + m11 * __ldg(xc + i11);
                }
                v0 = vv[0]; v1 = vv[1]; v2 = vv[2];
            }

            acc[p][0] = fmaf(v0, w40.x, acc[p][0]);
            acc[p][1] = fmaf(v0, w40.y, acc[p][1]);
            acc[p][2] = fmaf(v0, w40.z, acc[p][2]);
            acc[p][0] = fmaf(v1, w41.x, acc[p][0]);
            acc[p][1] = fmaf(v1, w41.y, acc[p][1]);
            acc[p][2] = fmaf(v1, w41.z, acc[p][2]);
            acc[p][0] = fmaf(v2, w42.x, acc[p][0]);
            acc[p][1] = fmaf(v2, w42.y, acc[p][1]);
            acc[p][2] = fmaf(v2, w42.z, acc[p][2]);
        }
    }

    // ---- store ----
    if (wo < WO) {
        const size_t plane = (size_t)HO * WO;
#pragma unroll
        for (int p = 0; p < 2; p++) {
            int ho = hoA + p;
            if (ho < HO) {
                size_t ob = (size_t)b * 3 * plane + (size_t)ho * WO + wo;
                out[ob]             = acc[p][0];
                out[ob + plane]     = acc[p][1];
                out[ob + 2 * plane] = acc[p][2];
            }
        }
    }
}

extern "C" void kernel_launch(void* const* d_in, const int* in_sizes, int n_in,
                              void* d_out, int out_size)
{
    const float* x  = (const float*)d_in[0];
    const float* w1 = (const float*)d_in[1];
    const float* b1 = (const float*)d_in[2];
    const float* w2 = (const float*)d_in[3];
    const float* b2 = (const float*)d_in[4];
    float* out = (float*)d_out;

    dim3 block(32, 4, 1);
    dim3 grid((WO + 31) / 32, (HO + 7) / 8, NB);
    deform_fused6<<<grid, block>>>(x, w1, b1, w2, b2, out);
}

// round 7
// speedup vs baseline: 1.0940x; 1.0940x over previous
#include <cuda_runtime.h>

#define IH 384
#define IW 384
#define HO 382
#define WO 382
#define NB 8
#define HALO 6
#define TH 22          // rows [ho0-6, ho0+15]
#define TW 46          // cols [wo0-6, wo0+39]
#define TILE_CH (TH * TW)   // 1012

typedef unsigned long long u64;

__device__ __forceinline__ u64 fma2(u64 a, u64 b, u64 c) {
    u64 d;
    asm("fma.rn.f32x2 %0, %1, %2, %3;" : "=l"(d) : "l"(a), "l"(b), "l"(c));
    return d;
}
__device__ __forceinline__ u64 pack2(float lo, float hi) {
    u64 r;
    asm("mov.b64 %0, {%1, %2};" : "=l"(r) : "f"(lo), "f"(hi));
    return r;
}
__device__ __forceinline__ void unpack2(u64 v, float& lo, float& hi) {
    asm("mov.b64 {%0, %1}, %2;" : "=f"(lo), "=f"(hi) : "l"(v));
}

__global__ __launch_bounds__(128, 5)
void deform_fused7(const float* __restrict__ x,
                   const float* __restrict__ w1,
                   const float* __restrict__ b1,
                   const float* __restrict__ w2,
                   const float* __restrict__ b2,
                   float* __restrict__ out)
{
    __shared__ float s_tile[3 * TILE_CH];
    __shared__ __align__(16) u64 s_w1p[9 * 28];    // [kk][j] packed (wdy, wdx); 16B-aligned stride
    __shared__ u64 s_b1p[9];
    __shared__ __align__(16) float4 s_w2v[9 * 3];  // [kk][c] = (w2[o=0], w2[o=1], w2[o=2], 0)
    __shared__ float s_b2[3];

    const int tid = threadIdx.y * 32 + threadIdx.x;

    // ---- weights to shared ----
    for (int i = tid; i < 9 * 27; i += 128) {
        int kk = i / 27, j = i % 27;
        s_w1p[kk * 28 + j] = pack2(w1[(2 * kk) * 27 + j], w1[(2 * kk + 1) * 27 + j]);
    }
    for (int i = tid; i < 9; i += 128) {
        s_w1p[i * 28 + 27] = 0ull;                 // pad slot
        s_b1p[i] = pack2(b1[2 * i], b1[2 * i + 1]);
    }
    if (tid < 27) {
        int kk = tid / 3, c = tid % 3;
        s_w2v[kk * 3 + c] = make_float4(w2[0 * 27 + c * 9 + kk],
                                        w2[1 * 27 + c * 9 + kk],
                                        w2[2 * 27 + c * 9 + kk], 0.f);
    }
    if (tid < 3) s_b2[tid] = b2[tid];

    const int wo0 = blockIdx.x * 32;
    const int ho0 = blockIdx.y * 8;
    const int b   = blockIdx.z;
    const float* __restrict__ xb = x + (size_t)b * 3 * IH * IW;

    const int rowBase = ho0 - HALO;
    const int colBase = wo0 - HALO;

    // ---- input tile to shared (zero-filled outside image) ----
    for (int i = tid; i < 3 * TILE_CH; i += 128) {
        int c  = i / TILE_CH;
        int rr = i - c * TILE_CH;
        int r  = rr / TW;
        int col = rr - r * TW;
        int gy = rowBase + r;
        int gx = colBase + col;
        float v = 0.f;
        if ((unsigned)gy < IH && (unsigned)gx < IW)
            v = __ldg(xb + ((size_t)c * IH + gy) * IW + gx);
        s_tile[i] = v;
    }
    __syncthreads();

    const int wo  = wo0 + threadIdx.x;
    const int hoA = ho0 + 2 * threadIdx.y;   // pixel pair rows hoA, hoA+1
    const int ltx = threadIdx.x + HALO;
    const int lty = 2 * threadIdx.y + HALO;

    // ---- window (4 rows x 3 cols x 3 ch) duplicated-packed in registers ----
    u64 wr2[3][4][3];
#pragma unroll
    for (int c = 0; c < 3; c++)
#pragma unroll
        for (int r = 0; r < 4; r++)
#pragma unroll
            for (int kw = 0; kw < 3; kw++) {
                float v = s_tile[c * TILE_CH + (lty + r) * TW + (ltx + kw)];
                wr2[c][r][kw] = pack2(v, v);
            }

    float acc[2][3];
#pragma unroll
    for (int p = 0; p < 2; p++)
#pragma unroll
        for (int o = 0; o < 3; o++) acc[p][o] = s_b2[o];

#pragma unroll 1
    for (int kk = 0; kk < 9; kk++) {
        // ---- offset conv for this kk, both pixels, packed (dy,dx) ----
        u64 a0 = s_b1p[kk];
        u64 a1 = a0;
        const u64* __restrict__ wp = &s_w1p[kk * 28];
#pragma unroll
        for (int j = 0; j < 27; j++) {
            int c  = j / 9;
            int kh = (j / 3) % 3;
            int kw = j % 3;
            u64 w = wp[j];
            a0 = fma2(wr2[c][kh][kw],     w, a0);
            a1 = fma2(wr2[c][kh + 1][kw], w, a1);
        }

        const int kh = kk / 3;
        const int kw = kk - 3 * kh;

        // w2 for this kk (broadcast LDS.128, shared by both pixels)
        float4 w40 = s_w2v[kk * 3 + 0];
        float4 w41 = s_w2v[kk * 3 + 1];
        float4 w42 = s_w2v[kk * 3 + 2];

#pragma unroll
        for (int p = 0; p < 2; p++) {
            float dy, dx;
            unpack2(p ? a1 : a0, dy, dx);
            float py = (float)(hoA + p + kh) + dy;
            float px = (float)(wo + kw) + dx;
            int y0 = __float2int_rd(py);
            int x0 = __float2int_rd(px);
            float wy = py - (float)y0;
            float wx = px - (float)x0;

            float c00 = (1.f - wy) * (1.f - wx);
            float c01 = (1.f - wy) * wx;
            float c10 = wy * (1.f - wx);
            float c11 = wy * wx;

            int ly0 = y0 - rowBase;
            int lx0 = x0 - colBase;

            float v0, v1, v2;
            if ((unsigned)ly0 <= TH - 2 && (unsigned)lx0 <= TW - 2) {
                // fast path: zero-filled tile makes validity masks redundant
                int t = ly0 * TW + lx0;
                {
                    const float* __restrict__ tc = &s_tile[t];
                    v0 = fmaf(c11, tc[TW + 1], fmaf(c10, tc[TW], fmaf(c01, tc[1], c00 * tc[0])));
                }
                {
                    const float* __restrict__ tc = &s_tile[TILE_CH + t];
                    v1 = fmaf(c11, tc[TW + 1], fmaf(c10, tc[TW], fmaf(c01, tc[1], c00 * tc[0])));
                }
                {
                    const float* __restrict__ tc = &s_tile[2 * TILE_CH + t];
                    v2 = fmaf(c11, tc[TW + 1], fmaf(c10, tc[TW], fmaf(c01, tc[1], c00 * tc[0])));
                }
            } else {
                // rare slow path: clamped global loads (exact reference semantics)
                bool vy0 = (y0 >= 0)  && (y0 <= IH - 1);
                bool vy1 = (y0 >= -1) && (y0 <= IH - 2);
                bool vx0 = (x0 >= 0)  && (x0 <= IW - 1);
                bool vx1 = (x0 >= -1) && (x0 <= IW - 2);
                float m00 = c00 * ((vy0 && vx0) ? 1.f : 0.f);
                float m01 = c01 * ((vy0 && vx1) ? 1.f : 0.f);
                float m10 = c10 * ((vy1 && vx0) ? 1.f : 0.f);
                float m11 = c11 * ((vy1 && vx1) ? 1.f : 0.f);
                int yc0 = min(max(y0, 0), IH - 1);
                int yc1 = min(max(y0 + 1, 0), IH - 1);
                int xc0 = min(max(x0, 0), IW - 1);
                int xc1 = min(max(x0 + 1, 0), IW - 1);
                int i00 = yc0 * IW + xc0;
                int i01 = yc0 * IW + xc1;
                int i10 = yc1 * IW + xc0;
                int i11 = yc1 * IW + xc1;
                float vv[3];
#pragma unroll
                for (int c = 0; c < 3; c++) {
                    const float* __restrict__ xc = xb + (size_t)c * IH * IW;
                    vv[c] = m00 * __ldg(xc + i00) + m01 * __ldg(xc + i01)
                          + m10 * __ldg(xc + i10) + m11 * __ldg(xc + i11);
                }
                v0 = vv[0]; v1 = vv[1]; v2 = vv[2];
            }

            acc[p][0] = fmaf(v0, w40.x, acc[p][0]);
            acc[p][1] = fmaf(v0, w40.y, acc[p][1]);
            acc[p][2] = fmaf(v0, w40.z, acc[p][2]);
            acc[p][0] = fmaf(v1, w41.x, acc[p][0]);
            acc[p][1] = fmaf(v1, w41.y, acc[p][1]);
            acc[p][2] = fmaf(v1, w41.z, acc[p][2]);
            acc[p][0] = fmaf(v2, w42.x, acc[p][0]);
            acc[p][1] = fmaf(v2, w42.y, acc[p][1]);
            acc[p][2] = fmaf(v2, w42.z, acc[p][2]);
        }
    }

    // ---- store ----
    if (wo < WO) {
        const size_t plane = (size_t)HO * WO;
#pragma unroll
        for (int p = 0; p < 2; p++) {
            int ho = hoA + p;
            if (ho < HO) {
                size_t ob = (size_t)b * 3 * plane + (size_t)ho * WO + wo;
                out[ob]             = acc[p][0];
                out[ob + plane]     = acc[p][1];
                out[ob + 2 * plane] = acc[p][2];
            }
        }
    }
}

extern "C" void kernel_launch(void* const* d_in, const int* in_sizes, int n_in,
                              void* d_out, int out_size)
{
    const float* x  = (const float*)d_in[0];
    const float* w1 = (const float*)d_in[1];
    const float* b1 = (const float*)d_in[2];
    const float* w2 = (const float*)d_in[3];
    const float* b2 = (const float*)d_in[4];
    float* out = (float*)d_out;

    dim3 block(32, 4, 1);
    dim3 grid((WO + 31) / 32, (HO + 7) / 8, NB);
    deform_fused7<<<grid, block>>>(x, w1, b1, w2, b2, out);
}

// round 8
// speedup vs baseline: 1.1407x; 1.0427x over previous
#include <cuda_runtime.h>

#define IH 384
#define IW 384
#define HO 382
#define WO 382
#define NB 8
#define HALO 6
#define TH 22          // rows [ho0-6, ho0+15]
#define TW 46          // cols [wo0-6, wo0+39]
#define TILE_CH (TH * TW)   // 1012

typedef unsigned long long u64;

__device__ __forceinline__ u64 fma2(u64 a, u64 b, u64 c) {
    u64 d;
    asm("fma.rn.f32x2 %0, %1, %2, %3;" : "=l"(d) : "l"(a), "l"(b), "l"(c));
    return d;
}
__device__ __forceinline__ u64 pack2(float lo, float hi) {
    u64 r;
    asm("mov.b64 %0, {%1, %2};" : "=l"(r) : "f"(lo), "f"(hi));
    return r;
}
__device__ __forceinline__ void unpack2(u64 v, float& lo, float& hi) {
    asm("mov.b64 {%0, %1}, %2;" : "=f"(lo), "=f"(hi) : "l"(v));
}

__global__ __launch_bounds__(128, 6)
void deform_fused8(const float* __restrict__ x,
                   const float* __restrict__ w1,
                   const float* __restrict__ b1,
                   const float* __restrict__ w2,
                   const float* __restrict__ b2,
                   float* __restrict__ out)
{
    __shared__ float s_tile[3 * TILE_CH];
    __shared__ __align__(16) u64 s_w1p[9 * 28];    // [kk][j] packed (wdy, wdx); slot 27 = 0 pad
    __shared__ u64 s_b1p[9];
    __shared__ __align__(16) float4 s_w2v[9 * 3];  // [kk][c] = (w2[o=0], w2[o=1], w2[o=2], 0)
    __shared__ float s_b2[3];

    const int tid = threadIdx.y * 32 + threadIdx.x;

    // ---- weights to shared ----
    for (int i = tid; i < 9 * 27; i += 128) {
        int kk = i / 27, j = i % 27;
        s_w1p[kk * 28 + j] = pack2(w1[(2 * kk) * 27 + j], w1[(2 * kk + 1) * 27 + j]);
    }
    for (int i = tid; i < 9; i += 128) {
        s_w1p[i * 28 + 27] = 0ull;                 // zero pad slot (even pairing of j-loop)
        s_b1p[i] = pack2(b1[2 * i], b1[2 * i + 1]);
    }
    if (tid < 27) {
        int kk = tid / 3, c = tid % 3;
        s_w2v[kk * 3 + c] = make_float4(w2[0 * 27 + c * 9 + kk],
                                        w2[1 * 27 + c * 9 + kk],
                                        w2[2 * 27 + c * 9 + kk], 0.f);
    }
    if (tid < 3) s_b2[tid] = b2[tid];

    const int wo0 = blockIdx.x * 32;
    const int ho0 = blockIdx.y * 8;
    const int b   = blockIdx.z;
    const float* __restrict__ xb = x + (size_t)b * 3 * IH * IW;

    const int rowBase = ho0 - HALO;
    const int colBase = wo0 - HALO;

    // ---- input tile to shared (zero-filled outside image) ----
    for (int i = tid; i < 3 * TILE_CH; i += 128) {
        int c  = i / TILE_CH;
        int rr = i - c * TILE_CH;
        int r  = rr / TW;
        int col = rr - r * TW;
        int gy = rowBase + r;
        int gx = colBase + col;
        float v = 0.f;
        if ((unsigned)gy < IH && (unsigned)gx < IW)
            v = __ldg(xb + ((size_t)c * IH + gy) * IW + gx);
        s_tile[i] = v;
    }
    __syncthreads();

    const int wo  = wo0 + threadIdx.x;
    const int hoA = ho0 + 2 * threadIdx.y;   // pixel pair rows hoA, hoA+1
    const int ltx = threadIdx.x + HALO;
    const int lty = 2 * threadIdx.y + HALO;

    // ---- window (4 rows x 3 cols x 3 ch) duplicated-packed in registers ----
    u64 wr2[3][4][3];
#pragma unroll
    for (int c = 0; c < 3; c++)
#pragma unroll
        for (int r = 0; r < 4; r++)
#pragma unroll
            for (int kw = 0; kw < 3; kw++) {
                float v = s_tile[c * TILE_CH + (lty + r) * TW + (ltx + kw)];
                wr2[c][r][kw] = pack2(v, v);
            }

    float acc[2][3];
#pragma unroll
    for (int p = 0; p < 2; p++)
#pragma unroll
        for (int o = 0; o < 3; o++) acc[p][o] = s_b2[o];

#pragma unroll 1
    for (int kk = 0; kk < 9; kk++) {
        // ---- offset conv for this kk, both pixels; weights via paired broadcast LDS.128 ----
        u64 a0 = s_b1p[kk];
        u64 a1 = a0;
        const ulonglong2* __restrict__ wq = (const ulonglong2*)&s_w1p[kk * 28];
#pragma unroll
        for (int jj = 0; jj < 14; jj++) {
            ulonglong2 w = wq[jj];
            {
                const int j = 2 * jj;
                const int c = j / 9, kh = (j / 3) % 3, kw = j % 3;
                a0 = fma2(wr2[c][kh][kw],     w.x, a0);
                a1 = fma2(wr2[c][kh + 1][kw], w.x, a1);
            }
            {
                const int j2 = 2 * jj + 1;
                const int j = (j2 < 27) ? j2 : 0;   // slot 27 is the zero weight: adds 0
                const int c = j / 9, kh = (j / 3) % 3, kw = j % 3;
                a0 = fma2(wr2[c][kh][kw],     w.y, a0);
                a1 = fma2(wr2[c][kh + 1][kw], w.y, a1);
            }
        }

        const int kh = kk / 3;
        const int kw = kk - 3 * kh;

        // w2 for this kk (broadcast LDS.128, shared by both pixels)
        float4 w40 = s_w2v[kk * 3 + 0];
        float4 w41 = s_w2v[kk * 3 + 1];
        float4 w42 = s_w2v[kk * 3 + 2];

#pragma unroll
        for (int p = 0; p < 2; p++) {
            float dy, dx;
            unpack2(p ? a1 : a0, dy, dx);
            float py = (float)(hoA + p + kh) + dy;
            float px = (float)(wo + kw) + dx;
            int y0 = __float2int_rd(py);
            int x0 = __float2int_rd(px);
            float wy = py - (float)y0;
            float wx = px - (float)x0;

            float c00 = (1.f - wy) * (1.f - wx);
            float c01 = (1.f - wy) * wx;
            float c10 = wy * (1.f - wx);
            float c11 = wy * wx;

            int ly0 = y0 - rowBase;
            int lx0 = x0 - colBase;

            float v0, v1, v2;
            if ((unsigned)ly0 <= TH - 2 && (unsigned)lx0 <= TW - 2) {
                // fast path: zero-filled tile makes validity masks redundant
                int t = ly0 * TW + lx0;
                {
                    const float* __restrict__ tc = &s_tile[t];
                    v0 = fmaf(c11, tc[TW + 1], fmaf(c10, tc[TW], fmaf(c01, tc[1], c00 * tc[0])));
                }
                {
                    const float* __restrict__ tc = &s_tile[TILE_CH + t];
                    v1 = fmaf(c11, tc[TW + 1], fmaf(c10, tc[TW], fmaf(c01, tc[1], c00 * tc[0])));
                }
                {
                    const float* __restrict__ tc = &s_tile[2 * TILE_CH + t];
                    v2 = fmaf(c11, tc[TW + 1], fmaf(c10, tc[TW], fmaf(c01, tc[1], c00 * tc[0])));
                }
            } else {
                // rare slow path: clamped global loads (exact reference semantics)
                bool vy0 = (y0 >= 0)  && (y0 <= IH - 1);
                bool vy1 = (y0 >= -1) && (y0 <= IH - 2);
                bool vx0 = (x0 >= 0)  && (x0 <= IW - 1);
                bool vx1 = (x0 >= -1) && (x0 <= IW - 2);
                float m00 = c00 * ((vy0 && vx0) ? 1.f : 0.f);
                float m01 = c01 * ((vy0 && vx1) ? 1.f : 0.f);
                float m10 = c10 * ((vy1 && vx0) ? 1.f : 0.f);
                float m11 = c11 * ((vy1 && vx1) ? 1.f : 0.f);
                int yc0 = min(max(y0, 0), IH - 1);
                int yc1 = min(max(y0 + 1, 0), IH - 1);
                int xc0 = min(max(x0, 0), IW - 1);
                int xc1 = min(max(x0 + 1, 0), IW - 1);
                int i00 = yc0 * IW + xc0;
                int i01 = yc0 * IW + xc1;
                int i10 = yc1 * IW + xc0;
                int i11 = yc1 * IW + xc1;
                float vv[3];
#pragma unroll
                for (int c = 0; c < 3; c++) {
                    const float* __restrict__ xc = xb + (size_t)c * IH * IW;
                    vv[c] = m00 * __ldg(xc + i00) + m01 * __ldg(xc + i01)
                          + m10 * __ldg(xc + i10) + m11 * __ldg(xc + i11);
                }
                v0 = vv[0]; v1 = vv[1]; v2 = vv[2];
            }

            acc[p][0] = fmaf(v0, w40.x, acc[p][0]);
            acc[p][1] = fmaf(v0, w40.y, acc[p][1]);
            acc[p][2] = fmaf(v0, w40.z, acc[p][2]);
            acc[p][0] = fmaf(v1, w41.x, acc[p][0]);
            acc[p][1] = fmaf(v1, w41.y, acc[p][1]);
            acc[p][2] = fmaf(v1, w41.z, acc[p][2]);
            acc[p][0] = fmaf(v2, w42.x, acc[p][0]);
            acc[p][1] = fmaf(v2, w42.y, acc[p][1]);
            acc[p][2] = fmaf(v2, w42.z, acc[p][2]);
        }
    }

    // ---- store ----
    if (wo < WO) {
        const size_t plane = (size_t)HO * WO;
#pragma unroll
        for (int p = 0; p < 2; p++) {
            int ho = hoA + p;
            if (ho < HO) {
                size_t ob = (size_t)b * 3 * plane + (size_t)ho * WO + wo;
                out[ob]             = acc[p][0];
                out[ob + plane]     = acc[p][1];
                out[ob + 2 * plane] = acc[p][2];
            }
        }
    }
}

extern "C" void kernel_launch(void* const* d_in, const int* in_sizes, int n_in,
                              void* d_out, int out_size)
{
    const float* x  = (const float*)d_in[0];
    const float* w1 = (const float*)d_in[1];
    const float* b1 = (const float*)d_in[2];
    const float* w2 = (const float*)d_in[3];
    const float* b2 = (const float*)d_in[4];
    float* out = (float*)d_out;

    dim3 block(32, 4, 1);
    dim3 grid((WO + 31) / 32, (HO + 7) / 8, NB);
    deform_fused8<<<grid, block>>>(x, w1, b1, w2, b2, out);
}

// round 9
// speedup vs baseline: 1.1498x; 1.0080x over previous
#include <cuda_runtime.h>

#define IH 384
#define IW 384
#define HO 382
#define WO 382
#define NB 8
#define HALO 6
#define TH 22          // rows [ho0-6, ho0+15]
#define TW 46          // cols [wo0-6, wo0+39]
#define TILE_CH (TH * TW)   // 1012

typedef unsigned long long u64;

__device__ __forceinline__ u64 fma2(u64 a, u64 b, u64 c) {
    u64 d;
    asm("fma.rn.f32x2 %0, %1, %2, %3;" : "=l"(d) : "l"(a), "l"(b), "l"(c));
    return d;
}
__device__ __forceinline__ u64 add2(u64 a, u64 b) {
    u64 d;
    asm("add.rn.f32x2 %0, %1, %2;" : "=l"(d) : "l"(a), "l"(b));
    return d;
}
__device__ __forceinline__ u64 pack2(float lo, float hi) {
    u64 r;
    asm("mov.b64 %0, {%1, %2};" : "=l"(r) : "f"(lo), "f"(hi));
    return r;
}
__device__ __forceinline__ void unpack2(u64 v, float& lo, float& hi) {
    asm("mov.b64 {%0, %1}, %2;" : "=f"(lo), "=f"(hi) : "l"(v));
}

__global__ __launch_bounds__(128, 6)
void deform_fused9(const float* __restrict__ x,
                   const float* __restrict__ w1,
                   const float* __restrict__ b1,
                   const float* __restrict__ w2,
                   const float* __restrict__ b2,
                   float* __restrict__ out)
{
    __shared__ float s_tile[3 * TILE_CH];
    __shared__ __align__(16) u64 s_w1p[9 * 28];    // [kk][j] packed (wdy, wdx); slot 27 = 0 pad
    __shared__ u64 s_b1p[9];
    __shared__ __align__(16) float4 s_w2v[9 * 3];  // [kk][c] = (w2[o=0], w2[o=1], w2[o=2], 0)
    __shared__ float s_b2[3];

    const int tid = threadIdx.y * 32 + threadIdx.x;

    // ---- weights to shared ----
    for (int i = tid; i < 9 * 27; i += 128) {
        int kk = i / 27, j = i % 27;
        s_w1p[kk * 28 + j] = pack2(w1[(2 * kk) * 27 + j], w1[(2 * kk + 1) * 27 + j]);
    }
    for (int i = tid; i < 9; i += 128) {
        s_w1p[i * 28 + 27] = 0ull;                 // zero pad slot (even pairing of j-loop)
        s_b1p[i] = pack2(b1[2 * i], b1[2 * i + 1]);
    }
    if (tid < 27) {
        int kk = tid / 3, c = tid % 3;
        s_w2v[kk * 3 + c] = make_float4(w2[0 * 27 + c * 9 + kk],
                                        w2[1 * 27 + c * 9 + kk],
                                        w2[2 * 27 + c * 9 + kk], 0.f);
    }
    if (tid < 3) s_b2[tid] = b2[tid];

    const int wo0 = blockIdx.x * 32;
    const int ho0 = blockIdx.y * 8;
    const int b   = blockIdx.z;
    const float* __restrict__ xb = x + (size_t)b * 3 * IH * IW;

    const int rowBase = ho0 - HALO;
    const int colBase = wo0 - HALO;

    // ---- input tile to shared (zero-filled outside image) ----
    for (int i = tid; i < 3 * TILE_CH; i += 128) {
        int c  = i / TILE_CH;
        int rr = i - c * TILE_CH;
        int r  = rr / TW;
        int col = rr - r * TW;
        int gy = rowBase + r;
        int gx = colBase + col;
        float v = 0.f;
        if ((unsigned)gy < IH && (unsigned)gx < IW)
            v = __ldg(xb + ((size_t)c * IH + gy) * IW + gx);
        s_tile[i] = v;
    }
    __syncthreads();

    const int wo  = wo0 + threadIdx.x;
    const int hoA = ho0 + 2 * threadIdx.y;   // pixel pair rows hoA, hoA+1
    const int ltx = threadIdx.x + HALO;
    const int lty = 2 * threadIdx.y + HALO;

    // ---- window (4 rows x 3 cols x 3 ch) duplicated-packed in registers ----
    u64 wr2[3][4][3];
#pragma unroll
    for (int c = 0; c < 3; c++)
#pragma unroll
        for (int r = 0; r < 4; r++)
#pragma unroll
            for (int kw = 0; kw < 3; kw++) {
                float v = s_tile[c * TILE_CH + (lty + r) * TW + (ltx + kw)];
                wr2[c][r][kw] = pack2(v, v);
            }

    float acc[2][3];
#pragma unroll
    for (int p = 0; p < 2; p++)
#pragma unroll
        for (int o = 0; o < 3; o++) acc[p][o] = s_b2[o];

#pragma unroll 3
    for (int kk = 0; kk < 9; kk++) {
        // ---- offset conv: 4 independent FFMA2 chains (a0a,a0b,a1a,a1b) ----
        u64 a0a = s_b1p[kk];
        u64 a1a = a0a;
        u64 a0b = pack2(0.f, 0.f);
        u64 a1b = a0b;
        const ulonglong2* __restrict__ wq = (const ulonglong2*)&s_w1p[kk * 28];
#pragma unroll
        for (int jj = 0; jj < 14; jj++) {
            ulonglong2 w = wq[jj];
            {
                const int j = 2 * jj;
                const int c = j / 9, kh = (j / 3) % 3, kw = j % 3;
                a0a = fma2(wr2[c][kh][kw],     w.x, a0a);
                a1a = fma2(wr2[c][kh + 1][kw], w.x, a1a);
            }
            {
                const int j2 = 2 * jj + 1;
                const int j = (j2 < 27) ? j2 : 0;   // slot 27 is the zero weight: adds 0
                const int c = j / 9, kh = (j / 3) % 3, kw = j % 3;
                a0b = fma2(wr2[c][kh][kw],     w.y, a0b);
                a1b = fma2(wr2[c][kh + 1][kw], w.y, a1b);
            }
        }
        u64 a0 = add2(a0a, a0b);
        u64 a1 = add2(a1a, a1b);

        const int kh = kk / 3;
        const int kw = kk - 3 * kh;

        // w2 for this kk (broadcast LDS.128, shared by both pixels)
        float4 w40 = s_w2v[kk * 3 + 0];
        float4 w41 = s_w2v[kk * 3 + 1];
        float4 w42 = s_w2v[kk * 3 + 2];

#pragma unroll
        for (int p = 0; p < 2; p++) {
            float dy, dx;
            unpack2(p ? a1 : a0, dy, dx);
            float py = (float)(hoA + p + kh) + dy;
            float px = (float)(wo + kw) + dx;
            int y0 = __float2int_rd(py);
            int x0 = __float2int_rd(px);
            float wy = py - (float)y0;
            float wx = px - (float)x0;

            float c00 = (1.f - wy) * (1.f - wx);
            float c01 = (1.f - wy) * wx;
            float c10 = wy * (1.f - wx);
            float c11 = wy * wx;

            int ly0 = y0 - rowBase;
            int lx0 = x0 - colBase;

            float v0, v1, v2;
            if ((unsigned)ly0 <= TH - 2 && (unsigned)lx0 <= TW - 2) {
                // fast path: zero-filled tile makes validity masks redundant
                int t = ly0 * TW + lx0;
                {
                    const float* __restrict__ tc = &s_tile[t];
                    v0 = fmaf(c11, tc[TW + 1], fmaf(c10, tc[TW], fmaf(c01, tc[1], c00 * tc[0])));
                }
                {
                    const float* __restrict__ tc = &s_tile[TILE_CH + t];
                    v1 = fmaf(c11, tc[TW + 1], fmaf(c10, tc[TW], fmaf(c01, tc[1], c00 * tc[0])));
                }
                {
                    const float* __restrict__ tc = &s_tile[2 * TILE_CH + t];
                    v2 = fmaf(c11, tc[TW + 1], fmaf(c10, tc[TW], fmaf(c01, tc[1], c00 * tc[0])));
                }
            } else {
                // rare slow path: clamped global loads (exact reference semantics)
                bool vy0 = (y0 >= 0)  && (y0 <= IH - 1);
                bool vy1 = (y0 >= -1) && (y0 <= IH - 2);
                bool vx0 = (x0 >= 0)  && (x0 <= IW - 1);
                bool vx1 = (x0 >= -1) && (x0 <= IW - 2);
                float m00 = c00 * ((vy0 && vx0) ? 1.f : 0.f);
                float m01 = c01 * ((vy0 && vx1) ? 1.f : 0.f);
                float m10 = c10 * ((vy1 && vx0) ? 1.f : 0.f);
                float m11 = c11 * ((vy1 && vx1) ? 1.f : 0.f);
                int yc0 = min(max(y0, 0), IH - 1);
                int yc1 = min(max(y0 + 1, 0), IH - 1);
                int xc0 = min(max(x0, 0), IW - 1);
                int xc1 = min(max(x0 + 1, 0), IW - 1);
                int i00 = yc0 * IW + xc0;
                int i01 = yc0 * IW + xc1;
                int i10 = yc1 * IW + xc0;
                int i11 = yc1 * IW + xc1;
                float vv[3];
#pragma unroll
                for (int c = 0; c < 3; c++) {
                    const float* __restrict__ xc = xb + (size_t)c * IH * IW;
                    vv[c] = m00 * __ldg(xc + i00) + m01 * __ldg(xc + i01)
                          + m10 * __ldg(xc + i10) + m11 * __ldg(xc + i11);
                }
                v0 = vv[0]; v1 = vv[1]; v2 = vv[2];
            }

            acc[p][0] = fmaf(v0, w40.x, acc[p][0]);
            acc[p][1] = fmaf(v0, w40.y, acc[p][1]);
            acc[p][2] = fmaf(v0, w40.z, acc[p][2]);
            acc[p][0] = fmaf(v1, w41.x, acc[p][0]);
            acc[p][1] = fmaf(v1, w41.y, acc[p][1]);
            acc[p][2] = fmaf(v1, w41.z, acc[p][2]);
            acc[p][0] = fmaf(v2, w42.x, acc[p][0]);
            acc[p][1] = fmaf(v2, w42.y, acc[p][1]);
            acc[p][2] = fmaf(v2, w42.z, acc[p][2]);
        }
    }

    // ---- store ----
    if (wo < WO) {
        const size_t plane = (size_t)HO * WO;
#pragma unroll
        for (int p = 0; p < 2; p++) {
            int ho = hoA + p;
            if (ho < HO) {
                size_t ob = (size_t)b * 3 * plane + (size_t)ho * WO + wo;
                out[ob]             = acc[p][0];
                out[ob + plane]     = acc[p][1];
                out[ob + 2 * plane] = acc[p][2];
            }
        }
    }
}

extern "C" void kernel_launch(void* const* d_in, const int* in_sizes, int n_in,
                              void* d_out, int out_size)
{
    const float* x  = (const float*)d_in[0];
    const float* w1 = (const float*)d_in[1];
    const float* b1 = (const float*)d_in[2];
    const float* w2 = (const float*)d_in[3];
    const float* b2 = (const float*)d_in[4];
    float* out = (float*)d_out;

    dim3 block(32, 4, 1);
    dim3 grid((WO + 31) / 32, (HO + 7) / 8, NB);
    deform_fused9<<<grid, block>>>(x, w1, b1, w2, b2, out);
}

// round 10
// speedup vs baseline: 1.2311x; 1.0707x over previous
#include <cuda_runtime.h>

#define IH 384
#define IW 384
#define HO 382
#define WO 382
#define NB 8
#define HALO 6
#define TH 22          // rows [ho0-6, ho0+15]
#define TW 46          // cols [wo0-6, wo0+39]
#define TILE_CH (TH * TW)   // 1012

typedef unsigned long long u64;

__device__ __forceinline__ u64 fma2(u64 a, u64 b, u64 c) {
    u64 d;
    asm("fma.rn.f32x2 %0, %1, %2, %3;" : "=l"(d) : "l"(a), "l"(b), "l"(c));
    return d;
}
__device__ __forceinline__ u64 add2(u64 a, u64 b) {
    u64 d;
    asm("add.rn.f32x2 %0, %1, %2;" : "=l"(d) : "l"(a), "l"(b));
    return d;
}
__device__ __forceinline__ u64 pack2(float lo, float hi) {
    u64 r;
    asm("mov.b64 %0, {%1, %2};" : "=l"(r) : "f"(lo), "f"(hi));
    return r;
}
__device__ __forceinline__ void unpack2(u64 v, float& lo, float& hi) {
    asm("mov.b64 {%0, %1}, %2;" : "=f"(lo), "=f"(hi) : "l"(v));
}

struct WPack {
    u64    w1p[9 * 28];   // [kk][j] packed (wdy, wdx); slot 27 = 0 pad
    u64    b1p[9];        // packed (b_dy, b_dx)
    float4 w2v[9 * 3];    // [kk][c] = (w2[o=0], w2[o=1], w2[o=2], 0)
    float  b2[3];
    float  pad;
};

__device__   WPack g_pack;   // scratch written by pack kernel
__constant__ WPack c_pack;   // read by main kernel via uniform/constant port

__global__ void pack_weights(const float* __restrict__ w1,
                             const float* __restrict__ b1,
                             const float* __restrict__ w2,
                             const float* __restrict__ b2)
{
    int i = threadIdx.x;
    if (i < 9 * 27) {
        int kk = i / 27, j = i % 27;
        g_pack.w1p[kk * 28 + j] = pack2(w1[(2 * kk) * 27 + j], w1[(2 * kk + 1) * 27 + j]);
    }
    if (i < 9) {
        g_pack.w1p[i * 28 + 27] = 0ull;
        g_pack.b1p[i] = pack2(b1[2 * i], b1[2 * i + 1]);
    }
    if (i < 27) {
        int kk = i / 3, c = i % 3;
        g_pack.w2v[kk * 3 + c] = make_float4(w2[0 * 27 + c * 9 + kk],
                                             w2[1 * 27 + c * 9 + kk],
                                             w2[2 * 27 + c * 9 + kk], 0.f);
    }
    if (i < 3) g_pack.b2[i] = b2[i];
    if (i == 0) g_pack.pad = 0.f;
}

__global__ __launch_bounds__(128, 6)
void deform_fused10(const float* __restrict__ x,
                    float* __restrict__ out)
{
    __shared__ float s_tile[3 * TILE_CH];

    const int tid = threadIdx.y * 32 + threadIdx.x;

    const int wo0 = blockIdx.x * 32;
    const int ho0 = blockIdx.y * 8;
    const int b   = blockIdx.z;
    const float* __restrict__ xb = x + (size_t)b * 3 * IH * IW;

    const int rowBase = ho0 - HALO;
    const int colBase = wo0 - HALO;

    // ---- input tile to shared (zero-filled outside image) ----
    for (int i = tid; i < 3 * TILE_CH; i += 128) {
        int c  = i / TILE_CH;
        int rr = i - c * TILE_CH;
        int r  = rr / TW;
        int col = rr - r * TW;
        int gy = rowBase + r;
        int gx = colBase + col;
        float v = 0.f;
        if ((unsigned)gy < IH && (unsigned)gx < IW)
            v = __ldg(xb + ((size_t)c * IH + gy) * IW + gx);
        s_tile[i] = v;
    }
    __syncthreads();

    const int wo  = wo0 + threadIdx.x;
    const int hoA = ho0 + 2 * threadIdx.y;   // pixel pair rows hoA, hoA+1
    const int ltx = threadIdx.x + HALO;
    const int lty = 2 * threadIdx.y + HALO;

    // ---- window (4 rows x 3 cols x 3 ch) duplicated-packed in registers ----
    u64 wr2[3][4][3];
#pragma unroll
    for (int c = 0; c < 3; c++)
#pragma unroll
        for (int r = 0; r < 4; r++)
#pragma unroll
            for (int kw = 0; kw < 3; kw++) {
                float v = s_tile[c * TILE_CH + (lty + r) * TW + (ltx + kw)];
                wr2[c][r][kw] = pack2(v, v);
            }

    float acc[2][3];
#pragma unroll
    for (int p = 0; p < 2; p++)
#pragma unroll
        for (int o = 0; o < 3; o++) acc[p][o] = c_pack.b2[o];

#pragma unroll 3
    for (int kk = 0; kk < 9; kk++) {
        // ---- offset conv: weights via constant/uniform port (no LSU traffic) ----
        u64 a0a = c_pack.b1p[kk];
        u64 a1a = a0a;
        u64 a0b = pack2(0.f, 0.f);
        u64 a1b = a0b;
#pragma unroll
        for (int jj = 0; jj < 14; jj++) {
            {
                const int j = 2 * jj;
                const int c = j / 9, kh = (j / 3) % 3, kw = j % 3;
                u64 w = c_pack.w1p[kk * 28 + j];
                a0a = fma2(wr2[c][kh][kw],     w, a0a);
                a1a = fma2(wr2[c][kh + 1][kw], w, a1a);
            }
            {
                const int j2 = 2 * jj + 1;
                const int j = (j2 < 27) ? j2 : 0;   // slot 27 is the zero weight: adds 0
                const int c = j / 9, kh = (j / 3) % 3, kw = j % 3;
                u64 w = c_pack.w1p[kk * 28 + ((j2 < 27) ? j2 : 27)];
                a0b = fma2(wr2[c][kh][kw],     w, a0b);
                a1b = fma2(wr2[c][kh + 1][kw], w, a1b);
            }
        }
        u64 a0 = add2(a0a, a0b);
        u64 a1 = add2(a1a, a1b);

        const int kh = kk / 3;
        const int kw = kk - 3 * kh;

        // w2 for this kk (constant/uniform port)
        float4 w40 = c_pack.w2v[kk * 3 + 0];
        float4 w41 = c_pack.w2v[kk * 3 + 1];
        float4 w42 = c_pack.w2v[kk * 3 + 2];

#pragma unroll
        for (int p = 0; p < 2; p++) {
            float dy, dx;
            unpack2(p ? a1 : a0, dy, dx);
            float py = (float)(hoA + p + kh) + dy;
            float px = (float)(wo + kw) + dx;
            int y0 = __float2int_rd(py);
            int x0 = __float2int_rd(px);
            float wy = py - (float)y0;
            float wx = px - (float)x0;

            float c00 = (1.f - wy) * (1.f - wx);
            float c01 = (1.f - wy) * wx;
            float c10 = wy * (1.f - wx);
            float c11 = wy * wx;

            int ly0 = y0 - rowBase;
            int lx0 = x0 - colBase;

            float v0, v1, v2;
            if ((unsigned)ly0 <= TH - 2 && (unsigned)lx0 <= TW - 2) {
                // fast path: zero-filled tile makes validity masks redundant
                int t = ly0 * TW + lx0;
                {
                    const float* __restrict__ tc = &s_tile[t];
                    v0 = fmaf(c11, tc[TW + 1], fmaf(c10, tc[TW], fmaf(c01, tc[1], c00 * tc[0])));
                }
                {
                    const float* __restrict__ tc = &s_tile[TILE_CH + t];
                    v1 = fmaf(c11, tc[TW + 1], fmaf(c10, tc[TW], fmaf(c01, tc[1], c00 * tc[0])));
                }
                {
                    const float* __restrict__ tc = &s_tile[2 * TILE_CH + t];
                    v2 = fmaf(c11, tc[TW + 1], fmaf(c10, tc[TW], fmaf(c01, tc[1], c00 * tc[0])));
                }
            } else {
                // rare slow path: clamped global loads (exact reference semantics)
                bool vy0 = (y0 >= 0)  && (y0 <= IH - 1);
                bool vy1 = (y0 >= -1) && (y0 <= IH - 2);
                bool vx0 = (x0 >= 0)  && (x0 <= IW - 1);
                bool vx1 = (x0 >= -1) && (x0 <= IW - 2);
                float m00 = c00 * ((vy0 && vx0) ? 1.f : 0.f);
                float m01 = c01 * ((vy0 && vx1) ? 1.f : 0.f);
                float m10 = c10 * ((vy1 && vx0) ? 1.f : 0.f);
                float m11 = c11 * ((vy1 && vx1) ? 1.f : 0.f);
                int yc0 = min(max(y0, 0), IH - 1);
                int yc1 = min(max(y0 + 1, 0), IH - 1);
                int xc0 = min(max(x0, 0), IW - 1);
                int xc1 = min(max(x0 + 1, 0), IW - 1);
                int i00 = yc0 * IW + xc0;
                int i01 = yc0 * IW + xc1;
                int i10 = yc1 * IW + xc0;
                int i11 = yc1 * IW + xc1;
                float vv[3];
#pragma unroll
                for (int c = 0; c < 3; c++) {
                    const float* __restrict__ xc = xb + (size_t)c * IH * IW;
                    vv[c] = m00 * __ldg(xc + i00) + m01 * __ldg(xc + i01)
                          + m10 * __ldg(xc + i10) + m11 * __ldg(xc + i11);
                }
                v0 = vv[0]; v1 = vv[1]; v2 = vv[2];
            }

            acc[p][0] = fmaf(v0, w40.x, acc[p][0]);
            acc[p][1] = fmaf(v0, w40.y, acc[p][1]);
            acc[p][2] = fmaf(v0, w40.z, acc[p][2]);
            acc[p][0] = fmaf(v1, w41.x, acc[p][0]);
            acc[p][1] = fmaf(v1, w41.y, acc[p][1]);
            acc[p][2] = fmaf(v1, w41.z, acc[p][2]);
            acc[p][0] = fmaf(v2, w42.x, acc[p][0]);
            acc[p][1] = fmaf(v2, w42.y, acc[p][1]);
            acc[p][2] = fmaf(v2, w42.z, acc[p][2]);
        }
    }

    // ---- store ----
    if (wo < WO) {
        const size_t plane = (size_t)HO * WO;
#pragma unroll
        for (int p = 0; p < 2; p++) {
            int ho = hoA + p;
            if (ho < HO) {
                size_t ob = (size_t)b * 3 * plane + (size_t)ho * WO + wo;
                out[ob]             = acc[p][0];
                out[ob + plane]     = acc[p][1];
                out[ob + 2 * plane] = acc[p][2];
            }
        }
    }
}

extern "C" void kernel_launch(void* const* d_in, const int* in_sizes, int n_in,
                              void* d_out, int out_size)
{
    const float* x  = (const float*)d_in[0];
    const float* w1 = (const float*)d_in[1];
    const float* b1 = (const float*)d_in[2];
    const float* w2 = (const float*)d_in[3];
    const float* b2 = (const float*)d_in[4];
    float* out = (float*)d_out;

    // 1) pack weights into __device__ scratch
    pack_weights<<<1, 256>>>(w1, b1, w2, b2);

    // 2) install into __constant__ (device-to-device async copy; graph-capturable)
    void* gaddr = nullptr;
    cudaGetSymbolAddress(&gaddr, g_pack);
    cudaMemcpyToSymbolAsync(c_pack, gaddr, sizeof(WPack), 0,
                            cudaMemcpyDeviceToDevice, 0);

    // 3) main kernel
    dim3 block(32, 4, 1);
    dim3 grid((WO + 31) / 32, (HO + 7) / 8, NB);
    deform_fused10<<<grid, block>>>(x, out);
}

// round 11
// speedup vs baseline: 1.2569x; 1.0210x over previous
#include <cuda_runtime.h>

#define IH 384
#define IW 384
#define HO 382
#define WO 382
#define NB 8
#define HALO 6
#define TH 22          // rows [ho0-6, ho0+15]
#define TW 46          // cols [wo0-6, wo0+39]
#define TILE_CH (TH * TW)   // 1012

typedef unsigned long long u64;

__device__ __forceinline__ u64 fma2(u64 a, u64 b, u64 c) {
    u64 d;
    asm("fma.rn.f32x2 %0, %1, %2, %3;" : "=l"(d) : "l"(a), "l"(b), "l"(c));
    return d;
}
__device__ __forceinline__ u64 add2(u64 a, u64 b) {
    u64 d;
    asm("add.rn.f32x2 %0, %1, %2;" : "=l"(d) : "l"(a), "l"(b));
    return d;
}
__device__ __forceinline__ u64 pack2(float lo, float hi) {
    u64 r;
    asm("mov.b64 %0, {%1, %2};" : "=l"(r) : "f"(lo), "f"(hi));
    return r;
}
__device__ __forceinline__ void unpack2(u64 v, float& lo, float& hi) {
    asm("mov.b64 {%0, %1}, %2;" : "=f"(lo), "=f"(hi) : "l"(v));
}

struct __align__(16) WPack {
    u64 w1p[9 * 28];   // [kk][j] packed (wdy, wdx); slot 27 = 0 pad; 224B/kk (16B aligned)
    u64 b1p[9];        // packed (b_dy, b_dx)
    u64 pad1;          // keep w2d 16B aligned
    u64 w2d[9 * 10];   // [kk][c*3+o] = dup(w2[o][c][kk]); slot 9 = 0 pad
    u64 b2d[3];        // dup(b2[o])
    u64 pad2;
};

__device__   WPack g_pack;   // scratch written by pack kernel
__constant__ WPack c_pack;   // read by main kernel via constant/uniform port

__global__ void pack_weights(const float* __restrict__ w1,
                             const float* __restrict__ b1,
                             const float* __restrict__ w2,
                             const float* __restrict__ b2)
{
    int i = threadIdx.x;
    if (i < 9 * 27) {
        int kk = i / 27, j = i % 27;
        g_pack.w1p[kk * 28 + j] = pack2(w1[(2 * kk) * 27 + j], w1[(2 * kk + 1) * 27 + j]);
    }
    if (i < 9) {
        g_pack.w1p[i * 28 + 27] = 0ull;
        g_pack.b1p[i] = pack2(b1[2 * i], b1[2 * i + 1]);
        g_pack.w2d[i * 10 + 9] = 0ull;
    }
    if (i < 81) {
        int kk = i / 9, r = i % 9;
        int c = r / 3, o = r % 3;
        float v = w2[o * 27 + c * 9 + kk];
        g_pack.w2d[kk * 10 + c * 3 + o] = pack2(v, v);
    }
    if (i < 3) { float v = b2[i]; g_pack.b2d[i] = pack2(v, v); }
    if (i == 0) { g_pack.pad1 = 0ull; g_pack.pad2 = 0ull; }
}

__global__ __launch_bounds__(128, 6)
void deform_fused11(const float* __restrict__ x,
                    float* __restrict__ out)
{
    __shared__ float s_tile[3 * TILE_CH];

    const int tid = threadIdx.y * 32 + threadIdx.x;

    const int wo0 = blockIdx.x * 32;
    const int ho0 = blockIdx.y * 8;
    const int b   = blockIdx.z;
    const float* __restrict__ xb = x + (size_t)b * 3 * IH * IW;

    const int rowBase = ho0 - HALO;
    const int colBase = wo0 - HALO;

    // ---- input tile to shared (zero-filled outside image) ----
    for (int i = tid; i < 3 * TILE_CH; i += 128) {
        int c  = i / TILE_CH;
        int rr = i - c * TILE_CH;
        int r  = rr / TW;
        int col = rr - r * TW;
        int gy = rowBase + r;
        int gx = colBase + col;
        float v = 0.f;
        if ((unsigned)gy < IH && (unsigned)gx < IW)
            v = __ldg(xb + ((size_t)c * IH + gy) * IW + gx);
        s_tile[i] = v;
    }
    __syncthreads();

    const int wo  = wo0 + threadIdx.x;
    const int hoA = ho0 + 2 * threadIdx.y;   // pixel pair rows hoA, hoA+1
    const int ltx = threadIdx.x + HALO;
    const int lty = 2 * threadIdx.y + HALO;

    // ---- window (4 rows x 3 cols x 3 ch) duplicated-packed in registers ----
    u64 wr2[3][4][3];
#pragma unroll
    for (int c = 0; c < 3; c++)
#pragma unroll
        for (int r = 0; r < 4; r++)
#pragma unroll
            for (int kw = 0; kw < 3; kw++) {
                float v = s_tile[c * TILE_CH + (lty + r) * TW + (ltx + kw)];
                wr2[c][r][kw] = pack2(v, v);
            }

    // packed (p0, p1) accumulators per output channel
    u64 accp[3];
#pragma unroll
    for (int o = 0; o < 3; o++) accp[o] = c_pack.b2d[o];

#pragma unroll 3
    for (int kk = 0; kk < 9; kk++) {
        // ---- offset conv: weights via LDCU.128 (paired), 4 independent FFMA2 chains ----
        u64 a0a = c_pack.b1p[kk];
        u64 a1a = a0a;
        u64 a0b = pack2(0.f, 0.f);
        u64 a1b = a0b;
        const ulonglong2* __restrict__ wq = (const ulonglong2*)&c_pack.w1p[kk * 28];
#pragma unroll
        for (int jj = 0; jj < 14; jj++) {
            ulonglong2 w = wq[jj];
            {
                const int j = 2 * jj;
                const int c = j / 9, kh = (j / 3) % 3, kw = j % 3;
                a0a = fma2(wr2[c][kh][kw],     w.x, a0a);
                a1a = fma2(wr2[c][kh + 1][kw], w.x, a1a);
            }
            {
                const int j2 = 2 * jj + 1;
                const int j = (j2 < 27) ? j2 : 0;   // slot 27 is the zero weight: adds 0
                const int c = j / 9, kh = (j / 3) % 3, kw = j % 3;
                a0b = fma2(wr2[c][kh][kw],     w.y, a0b);
                a1b = fma2(wr2[c][kh + 1][kw], w.y, a1b);
            }
        }
        u64 a0 = add2(a0a, a0b);
        u64 a1 = add2(a1a, a1b);

        const int kh = kk / 3;
        const int kw = kk - 3 * kh;

        // dup'd w2 for this kk via LDCU.128 (5 paired loads cover 9 weights + pad)
        u64 w2v[9];
        {
            const ulonglong2* __restrict__ w2q = (const ulonglong2*)&c_pack.w2d[kk * 10];
            ulonglong2 t0 = w2q[0], t1 = w2q[1], t2 = w2q[2], t3 = w2q[3];
            w2v[0] = t0.x; w2v[1] = t0.y;
            w2v[2] = t1.x; w2v[3] = t1.y;
            w2v[4] = t2.x; w2v[5] = t2.y;
            w2v[6] = t3.x; w2v[7] = t3.y;
            w2v[8] = c_pack.w2d[kk * 10 + 8];
        }

        float vch[2][3];
#pragma unroll
        for (int p = 0; p < 2; p++) {
            float dy, dx;
            unpack2(p ? a1 : a0, dy, dx);
            float py = (float)(hoA + p + kh) + dy;
            float px = (float)(wo + kw) + dx;
            int y0 = __float2int_rd(py);
            int x0 = __float2int_rd(px);
            float wy = py - (float)y0;
            float wx = px - (float)x0;

            float c00 = (1.f - wy) * (1.f - wx);
            float c01 = (1.f - wy) * wx;
            float c10 = wy * (1.f - wx);
            float c11 = wy * wx;

            int ly0 = y0 - rowBase;
            int lx0 = x0 - colBase;

            if ((unsigned)ly0 <= TH - 2 && (unsigned)lx0 <= TW - 2) {
                // fast path: zero-filled tile makes validity masks redundant
                int t = ly0 * TW + lx0;
                {
                    const float* __restrict__ tc = &s_tile[t];
                    vch[p][0] = fmaf(c11, tc[TW + 1], fmaf(c10, tc[TW], fmaf(c01, tc[1], c00 * tc[0])));
                }
                {
                    const float* __restrict__ tc = &s_tile[TILE_CH + t];
                    vch[p][1] = fmaf(c11, tc[TW + 1], fmaf(c10, tc[TW], fmaf(c01, tc[1], c00 * tc[0])));
                }
                {
                    const float* __restrict__ tc = &s_tile[2 * TILE_CH + t];
                    vch[p][2] = fmaf(c11, tc[TW + 1], fmaf(c10, tc[TW], fmaf(c01, tc[1], c00 * tc[0])));
                }
            } else {
                // rare slow path: clamped global loads (exact reference semantics)
                bool vy0 = (y0 >= 0)  && (y0 <= IH - 1);
                bool vy1 = (y0 >= -1) && (y0 <= IH - 2);
                bool vx0 = (x0 >= 0)  && (x0 <= IW - 1);
                bool vx1 = (x0 >= -1) && (x0 <= IW - 2);
                float m00 = c00 * ((vy0 && vx0) ? 1.f : 0.f);
                float m01 = c01 * ((vy0 && vx1) ? 1.f : 0.f);
                float m10 = c10 * ((vy1 && vx0) ? 1.f : 0.f);
                float m11 = c11 * ((vy1 && vx1) ? 1.f : 0.f);
                int yc0 = min(max(y0, 0), IH - 1);
                int yc1 = min(max(y0 + 1, 0), IH - 1);
                int xc0 = min(max(x0, 0), IW - 1);
                int xc1 = min(max(x0 + 1, 0), IW - 1);
                int i00 = yc0 * IW + xc0;
                int i01 = yc0 * IW + xc1;
                int i10 = yc1 * IW + xc0;
                int i11 = yc1 * IW + xc1;
#pragma unroll
                for (int c = 0; c < 3; c++) {
                    const float* __restrict__ xc = xb + (size_t)c * IH * IW;
                    vch[p][c] = m00 * __ldg(xc + i00) + m01 * __ldg(xc + i01)
                              + m10 * __ldg(xc + i10) + m11 * __ldg(xc + i11);
                }
            }
        }

        // ---- packed einsum: acc[o] += dup(w2[o][c][kk]) * (v_p0, v_p1) ----
#pragma unroll
        for (int c = 0; c < 3; c++) {
            u64 vp = pack2(vch[0][c], vch[1][c]);
            accp[0] = fma2(w2v[c * 3 + 0], vp, accp[0]);
            accp[1] = fma2(w2v[c * 3 + 1], vp, accp[1]);
            accp[2] = fma2(w2v[c * 3 + 2], vp, accp[2]);
        }
    }

    // ---- store ----
    if (wo < WO) {
        const size_t plane = (size_t)HO * WO;
        const size_t base  = (size_t)b * 3 * plane + (size_t)hoA * WO + wo;
        float a0, a1;
#pragma unroll
        for (int o = 0; o < 3; o++) {
            unpack2(accp[o], a0, a1);
            if (hoA < HO)     out[base + o * plane]      = a0;
            if (hoA + 1 < HO) out[base + o * plane + WO] = a1;
        }
    }
}

extern "C" void kernel_launch(void* const* d_in, const int* in_sizes, int n_in,
                              void* d_out, int out_size)
{
    const float* x  = (const float*)d_in[0];
    const float* w1 = (const float*)d_in[1];
    const float* b1 = (const float*)d_in[2];
    const float* w2 = (const float*)d_in[3];
    const float* b2 = (const float*)d_in[4];
    float* out = (float*)d_out;

    // 1) pack weights into __device__ scratch
    pack_weights<<<1, 256>>>(w1, b1, w2, b2);

    // 2) install into __constant__ (device-to-device async copy; graph-capturable)
    void* gaddr = nullptr;
    cudaGetSymbolAddress(&gaddr, g_pack);
    cudaMemcpyToSymbolAsync(c_pack, gaddr, sizeof(WPack), 0,
                            cudaMemcpyDeviceToDevice, 0);

    // 3) main kernel
    dim3 block(32, 4, 1);
    dim3 grid((WO + 31) / 32, (HO + 7) / 8, NB);
    deform_fused11<<<grid, block>>>(x, out);
}